// round 14
// baseline (speedup 1.0000x reference)
#include <cuda_runtime.h>
#include <cuda_fp16.h>
#include <cuda_bf16.h>
#include <mma.h>

using namespace nvcuda;

#define N_NODES   50000
#define N_EDGES   800000
#define IN_CH     128
#define HID       64
#define N_GRAPHS  256
#define N_CLASSES 10
#define CAP       64      // fixed bucket capacity (max degree ~40 for Poisson(16))

// ---------------- scratch (static device globals; no allocation) ------------
// Buffers that must start zeroed are re-zeroed at the END of each run
// (last block of k_agg2_final), so every replay starts from the same state.
__device__ int      g_cnt[N_NODES];            // per-node edge count
__device__ float    g_dinv[N_NODES];
__device__ int      g_csr[N_NODES * CAP];      // fixed-stride buckets of src ids
__device__ __half   g_hw[N_NODES * 64];        // X@W result, fp16 (both layers)
__device__ __half   g_agg1[N_NODES * 64];      // layer-1 output (post ReLU, fp16)
__device__ float    g_pooled[N_GRAPHS * 64];
__device__ int      g_counts[N_GRAPHS];
__device__ unsigned g_ticket;                  // agg2 last-block ticket (self-reset)

// ---------------- batch histogram (side stream) -------------------------------
__global__ void k_counts(const int* __restrict__ batch, int* __restrict__ counts) {
    int i = blockIdx.x * blockDim.x + threadIdx.x;
    if (i < N_NODES) atomicAdd(&counts[batch[i]], 1);
}

// bucket scatter over an edge range [base, base+count)
__global__ void k_csr(const int* __restrict__ src, const int* __restrict__ dst,
                      int base, int count,
                      int* __restrict__ cnt, int* __restrict__ csr) {
    int e = base + blockIdx.x * blockDim.x + threadIdx.x;
    if (e >= base + count) return;
    int s = src[e];
    int d = dst[e];
    int pos = atomicAdd(&cnt[d], 1);
    pos = min(pos, CAP - 1);   // safety clamp (never hit for this degree dist)
    csr[d * CAP + pos] = s;
}

// dinv from cnt (tiny)
__global__ void k_dinv(const int* __restrict__ cnt, float* __restrict__ dinv) {
    int i = blockIdx.x * blockDim.x + threadIdx.x;
    if (i < N_NODES) dinv[i] = rsqrtf((float)cnt[i] + 1.0f);
}

// ---------------- wmma GEMM: H[N x 64](fp16) = A[N x FIN] @ W[FIN x 64] -----
// SCALE: epilogue multiplies row by dinv[row] before fp16 pack (pre-scaled H).
template <int FIN, bool AHALF, bool SCALE>
__global__ __launch_bounds__(256) void k_gemm_wmma(
    const void* __restrict__ Ain, const float* __restrict__ W,
    const float* __restrict__ dinv, __half* __restrict__ H) {
    constexpr int LDA = FIN + 16;
    constexpr int LDW = 64 + 16;  // 80
    constexpr int LDC = 72;
    constexpr int A_BYTES = 64 * LDA * 2;
    constexpr int W_BYTES = FIN * LDW * 2;
    constexpr int C_BYTES = 64 * LDC * 4;
    constexpr int S_BYTES = (A_BYTES + W_BYTES) > C_BYTES ? (A_BYTES + W_BYTES) : C_BYTES;
    __shared__ __align__(32) char sraw[S_BYTES];
    __half* Ah = (__half*)sraw;
    __half* Wh = (__half*)(sraw + A_BYTES);
    float*  Cs = (float*)sraw;   // aliases Ah/Wh after compute is done

    const int t  = threadIdx.x;
    const int m0 = blockIdx.x * 64;

    if (AHALF) {
        const __half* A = (const __half*)Ain;
        for (int idx = t; idx < 64 * (FIN / 8); idx += 256) {
            int m  = idx / (FIN / 8);
            int kk = idx % (FIN / 8);
            int row = m0 + m;
            uint4 v = make_uint4(0u, 0u, 0u, 0u);
            if (row < N_NODES) v = *(const uint4*)(A + (size_t)row * FIN + kk * 8);
            *(uint4*)&Ah[m * LDA + kk * 8] = v;
        }
    } else {
        const float* A = (const float*)Ain;
        for (int idx = t; idx < 64 * (FIN / 4); idx += 256) {
            int m  = idx / (FIN / 4);
            int kk = idx % (FIN / 4);
            int row = m0 + m;
            float4 v = make_float4(0.f, 0.f, 0.f, 0.f);
            if (row < N_NODES) v = __ldg((const float4*)(A + (size_t)row * FIN) + kk);
            __half2 h0 = __floats2half2_rn(v.x, v.y);
            __half2 h1 = __floats2half2_rn(v.z, v.w);
            *(__half2*)&Ah[m * LDA + kk * 4]     = h0;
            *(__half2*)&Ah[m * LDA + kk * 4 + 2] = h1;
        }
    }
    for (int idx = t; idx < FIN * 16; idx += 256) {
        int k  = idx / 16;
        int c4 = idx % 16;
        float4 v = __ldg((const float4*)(W + (size_t)k * 64) + c4);
        __half2 h0 = __floats2half2_rn(v.x, v.y);
        __half2 h1 = __floats2half2_rn(v.z, v.w);
        *(__half2*)&Wh[k * LDW + c4 * 4]     = h0;
        *(__half2*)&Wh[k * LDW + c4 * 4 + 2] = h1;
    }
    __syncthreads();

    const int wid = t >> 5;
    const int wm  = wid >> 1;   // 0..3
    const int wn  = wid & 1;    // 0..1

    wmma::fragment<wmma::accumulator, 16, 16, 16, float> c0, c1;
    wmma::fill_fragment(c0, 0.0f);
    wmma::fill_fragment(c1, 0.0f);

#pragma unroll
    for (int k = 0; k < FIN; k += 16) {
        wmma::fragment<wmma::matrix_a, 16, 16, 16, __half, wmma::row_major> a;
        wmma::load_matrix_sync(a, &Ah[(wm * 16) * LDA + k], LDA);
        wmma::fragment<wmma::matrix_b, 16, 16, 16, __half, wmma::row_major> b0, b1;
        wmma::load_matrix_sync(b0, &Wh[k * LDW + wn * 32], LDW);
        wmma::load_matrix_sync(b1, &Wh[k * LDW + wn * 32 + 16], LDW);
        wmma::mma_sync(c0, a, b0, c0);
        wmma::mma_sync(c1, a, b1, c1);
    }

    __syncthreads();
    wmma::store_matrix_sync(&Cs[(wm * 16) * LDC + wn * 32],      c0, LDC, wmma::mem_row_major);
    wmma::store_matrix_sync(&Cs[(wm * 16) * LDC + wn * 32 + 16], c1, LDC, wmma::mem_row_major);
    __syncthreads();

    for (int idx = t; idx < 64 * 16; idx += 256) {
        int m  = idx >> 4;
        int c4 = idx & 15;
        int row = m0 + m;
        if (row < N_NODES) {
            float4 v = *(float4*)&Cs[m * LDC + c4 * 4];
            if (SCALE) {
                float di = dinv[row];
                v.x *= di; v.y *= di; v.z *= di; v.w *= di;
            }
            __half2 h0 = __floats2half2_rn(v.x, v.y);
            __half2 h1 = __floats2half2_rn(v.z, v.w);
            uint2 p = make_uint2(*(unsigned*)&h0, *(unsigned*)&h1);
            *(uint2*)(H + (size_t)row * 64 + c4 * 4) = p;
        }
    }
}

// ---------------- gather aggregation (fp16 gather, fp32 accumulate) ----------
__device__ __forceinline__ void acc_row(float acc[8], float nm, uint4 r) {
    float2 f0 = __half22float2(*(__half2*)&r.x);
    float2 f1 = __half22float2(*(__half2*)&r.y);
    float2 f2 = __half22float2(*(__half2*)&r.z);
    float2 f3 = __half22float2(*(__half2*)&r.w);
    acc[0] = fmaf(nm, f0.x, acc[0]); acc[1] = fmaf(nm, f0.y, acc[1]);
    acc[2] = fmaf(nm, f1.x, acc[2]); acc[3] = fmaf(nm, f1.y, acc[3]);
    acc[4] = fmaf(nm, f2.x, acc[4]); acc[5] = fmaf(nm, f2.y, acc[5]);
    acc[6] = fmaf(nm, f3.x, acc[6]); acc[7] = fmaf(nm, f3.y, acc[7]);
}

__device__ __forceinline__ void acc_row_add(float acc[8], uint4 r) {
    float2 f0 = __half22float2(*(__half2*)&r.x);
    float2 f1 = __half22float2(*(__half2*)&r.y);
    float2 f2 = __half22float2(*(__half2*)&r.z);
    float2 f3 = __half22float2(*(__half2*)&r.w);
    acc[0] += f0.x; acc[1] += f0.y;
    acc[2] += f1.x; acc[3] += f1.y;
    acc[4] += f2.x; acc[5] += f2.y;
    acc[6] += f3.x; acc[7] += f3.y;
}

// Layer 1: per-edge norm = dinv[src]*di; writes fp16, ReLU.
__global__ __launch_bounds__(256) void k_agg1(
    const int* __restrict__ cnt, const float* __restrict__ dinv,
    const int* __restrict__ csr, const __half* __restrict__ h,
    const float* __restrict__ bias, __half* __restrict__ out16) {
    int tid = blockIdx.x * blockDim.x + threadIdx.x;
    int n   = tid >> 3;
    int sub = tid & 7;
    if (n >= N_NODES) return;

    int deg = cnt[n];
    const int* bucket = csr + n * CAP;
    float di = dinv[n];

    float acc[8];
    {
        float s2 = di * di;
        uint4 raw = *(const uint4*)(h + (size_t)n * 64 + sub * 8);
        float4 bb0 = __ldg((const float4*)bias + sub * 2);
        float4 bb1 = __ldg((const float4*)bias + sub * 2 + 1);
        float2 f0 = __half22float2(*(__half2*)&raw.x);
        float2 f1 = __half22float2(*(__half2*)&raw.y);
        float2 f2 = __half22float2(*(__half2*)&raw.z);
        float2 f3 = __half22float2(*(__half2*)&raw.w);
        acc[0] = fmaf(f0.x, s2, bb0.x); acc[1] = fmaf(f0.y, s2, bb0.y);
        acc[2] = fmaf(f1.x, s2, bb0.z); acc[3] = fmaf(f1.y, s2, bb0.w);
        acc[4] = fmaf(f2.x, s2, bb1.x); acc[5] = fmaf(f2.y, s2, bb1.y);
        acc[6] = fmaf(f3.x, s2, bb1.z); acc[7] = fmaf(f3.y, s2, bb1.w);
    }

    int j = 0;
    for (; j + 4 <= deg; j += 4) {
        int4 sv = *(const int4*)(bucket + j);
        float n0 = dinv[sv.x] * di;
        float n1 = dinv[sv.y] * di;
        float n2 = dinv[sv.z] * di;
        float n3 = dinv[sv.w] * di;
        uint4 r0 = *(const uint4*)(h + (size_t)sv.x * 64 + sub * 8);
        uint4 r1 = *(const uint4*)(h + (size_t)sv.y * 64 + sub * 8);
        uint4 r2 = *(const uint4*)(h + (size_t)sv.z * 64 + sub * 8);
        uint4 r3 = *(const uint4*)(h + (size_t)sv.w * 64 + sub * 8);
        acc_row(acc, n0, r0);
        acc_row(acc, n1, r1);
        acc_row(acc, n2, r2);
        acc_row(acc, n3, r3);
    }
    for (; j < deg; j++) {
        int s0 = bucket[j];
        float n0 = dinv[s0] * di;
        uint4 r0 = *(const uint4*)(h + (size_t)s0 * 64 + sub * 8);
        acc_row(acc, n0, r0);
    }

#pragma unroll
    for (int c = 0; c < 8; c++) acc[c] = fmaxf(acc[c], 0.0f);

    __half2 h0 = __floats2half2_rn(acc[0], acc[1]);
    __half2 h1 = __floats2half2_rn(acc[2], acc[3]);
    __half2 h2 = __floats2half2_rn(acc[4], acc[5]);
    __half2 h3 = __floats2half2_rn(acc[6], acc[7]);
    uint4 p = make_uint4(*(unsigned*)&h0, *(unsigned*)&h1,
                         *(unsigned*)&h2, *(unsigned*)&h3);
    *(uint4*)(out16 + (size_t)n * 64 + sub * 8) = p;
}

// Layer 2 aggregate (hs PRE-SCALED by dinv; pure-sum inner loop) + mean-pool,
// then LAST BLOCK runs the classifier + scratch cleanup.
// __launch_bounds__(256, 6) caps registers (~42) so the epilogue cannot
// deflate mainloop occupancy — the epilogue spills to local, which is fine
// since it executes once on a single block.
__global__ __launch_bounds__(256, 6) void k_agg2_final(
    const int* __restrict__ cnt, const float* __restrict__ dinv,
    const int* __restrict__ csr, const __half* __restrict__ hs,
    const float* __restrict__ bias, const int* __restrict__ batch,
    float* __restrict__ pooled, int* __restrict__ counts,
    const float* __restrict__ Wl, const float* __restrict__ bl,
    float* __restrict__ out, int* __restrict__ cnt_w,
    unsigned* __restrict__ ticket) {
    int tid = blockIdx.x * blockDim.x + threadIdx.x;
    int n   = tid >> 3;
    int sub = tid & 7;

    bool wrote = false;
    if (n < N_NODES) {
        int deg = cnt[n];
        const int* bucket = csr + n * CAP;
        float di = dinv[n];

        float acc[8];
        {
            uint4 raw = *(const uint4*)(hs + (size_t)n * 64 + sub * 8);
            float2 f0 = __half22float2(*(__half2*)&raw.x);
            float2 f1 = __half22float2(*(__half2*)&raw.y);
            float2 f2 = __half22float2(*(__half2*)&raw.z);
            float2 f3 = __half22float2(*(__half2*)&raw.w);
            acc[0] = f0.x; acc[1] = f0.y; acc[2] = f1.x; acc[3] = f1.y;
            acc[4] = f2.x; acc[5] = f2.y; acc[6] = f3.x; acc[7] = f3.y;
        }

        int j = 0;
        for (; j + 4 <= deg; j += 4) {
            int4 sv = *(const int4*)(bucket + j);
            uint4 r0 = *(const uint4*)(hs + (size_t)sv.x * 64 + sub * 8);
            uint4 r1 = *(const uint4*)(hs + (size_t)sv.y * 64 + sub * 8);
            uint4 r2 = *(const uint4*)(hs + (size_t)sv.z * 64 + sub * 8);
            uint4 r3 = *(const uint4*)(hs + (size_t)sv.w * 64 + sub * 8);
            acc_row_add(acc, r0);
            acc_row_add(acc, r1);
            acc_row_add(acc, r2);
            acc_row_add(acc, r3);
        }
        for (; j < deg; j++) {
            int s0 = bucket[j];
            uint4 r0 = *(const uint4*)(hs + (size_t)s0 * 64 + sub * 8);
            acc_row_add(acc, r0);
        }

        float4 bb0 = __ldg((const float4*)bias + sub * 2);
        float4 bb1 = __ldg((const float4*)bias + sub * 2 + 1);
        float4 a0 = make_float4(fmaf(acc[0], di, bb0.x), fmaf(acc[1], di, bb0.y),
                                fmaf(acc[2], di, bb0.z), fmaf(acc[3], di, bb0.w));
        float4 a1 = make_float4(fmaf(acc[4], di, bb1.x), fmaf(acc[5], di, bb1.y),
                                fmaf(acc[6], di, bb1.z), fmaf(acc[7], di, bb1.w));

        int g = batch[n];
        atomicAdd((float4*)&pooled[(size_t)g * 64 + sub * 8], a0);
        atomicAdd((float4*)&pooled[(size_t)g * 64 + sub * 8 + 4], a1);
        wrote = true;
    }

    // ---- last-block epilogue (decoupled-lookback release pattern) ----
    if (wrote) __threadfence();   // order this thread's RED.ADDs before ticket
    __syncthreads();
    __shared__ bool s_last;
    if (threadIdx.x == 0) {
        unsigned old = atomicInc(ticket, gridDim.x - 1);  // wraps -> self-reset
        s_last = (old == gridDim.x - 1);
    }
    __syncthreads();
    if (!s_last) return;

    int t = threadIdx.x;
    // classifier: out[g, j] = (pooled[g]/count[g]) . Wl[:, j] + bl[j]
#pragma unroll 1
    for (int o = t; o < N_GRAPHS * N_CLASSES; o += 256) {
        int g = o / N_CLASSES;
        int j = o - g * N_CLASSES;
        float s = 0.0f;
#pragma unroll 1
        for (int c = 0; c < 64; c++)
            s += __ldcg(&pooled[g * 64 + c]) * Wl[c * N_CLASSES + j];
        float cn = fmaxf((float)__ldcg(&counts[g]), 1.0f);
        out[o] = s / cn + bl[j];
    }
    __syncthreads();
    // cleanup for next replay (all other blocks finished their reads before
    // arriving at the ticket)
#pragma unroll 1
    for (int i = t; i < N_GRAPHS * 64 / 4; i += 256)
        ((float4*)pooled)[i] = make_float4(0.f, 0.f, 0.f, 0.f);
    if (t < N_GRAPHS) counts[t] = 0;
#pragma unroll 1
    for (int i = t; i < N_NODES / 4; i += 256)
        ((int4*)cnt_w)[i] = make_int4(0, 0, 0, 0);
}

// ---------------- host launch -------------------------------------------------
template <typename T, typename S>
static T* sym_addr(const S& sym) {
    void* p = nullptr;
    cudaGetSymbolAddress(&p, sym);
    return (T*)p;
}

extern "C" void kernel_launch(void* const* d_in, const int* in_sizes, int n_in,
                              void* d_out, int out_size) {
    const float* x     = (const float*)d_in[0];
    const int*   ei    = (const int*)d_in[1];
    const int*   srcp  = ei;
    const int*   dstp  = ei + N_EDGES;
    const int*   batch = (const int*)d_in[3];
    const float* W1 = (const float*)d_in[4];
    const float* b1 = (const float*)d_in[5];
    const float* W2 = (const float*)d_in[6];
    const float* b2 = (const float*)d_in[7];
    const float* Wl = (const float*)d_in[8];
    const float* bl = (const float*)d_in[9];
    float* out = (float*)d_out;

    static int*      p_cnt    = nullptr;
    static float*    p_dinv   = nullptr;
    static int*      p_csr    = nullptr;
    static __half*   p_hw     = nullptr;
    static __half*   p_agg1   = nullptr;
    static float*    p_pooled = nullptr;
    static int*      p_counts = nullptr;
    static unsigned* p_ticket = nullptr;
    static cudaStream_t s_side = nullptr;
    static cudaEvent_t  ev_fork = nullptr, ev_csrb = nullptr,
                        ev_gemm = nullptr, ev_cnt = nullptr;
    if (!p_cnt) {
        p_cnt    = sym_addr<int>(g_cnt);
        p_dinv   = sym_addr<float>(g_dinv);
        p_csr    = sym_addr<int>(g_csr);
        p_hw     = sym_addr<__half>(g_hw);
        p_agg1   = sym_addr<__half>(g_agg1);
        p_pooled = sym_addr<float>(g_pooled);
        p_counts = sym_addr<int>(g_counts);
        p_ticket = sym_addr<unsigned>(g_ticket);
        cudaStreamCreateWithFlags(&s_side, cudaStreamNonBlocking);
        cudaEventCreateWithFlags(&ev_fork, cudaEventDisableTiming);
        cudaEventCreateWithFlags(&ev_csrb, cudaEventDisableTiming);
        cudaEventCreateWithFlags(&ev_gemm, cudaEventDisableTiming);
        cudaEventCreateWithFlags(&ev_cnt,  cudaEventDisableTiming);
    }

    const int B = 256;
    const int EHALF = N_EDGES / 2;

    // fork: side stream runs the second csr half, then gemm1, then counts
    cudaEventRecord(ev_fork, 0);
    cudaStreamWaitEvent(s_side, ev_fork, 0);
    k_csr<<<(EHALF + B - 1) / B, B, 0, s_side>>>(srcp, dstp, EHALF, EHALF, p_cnt, p_csr);
    cudaEventRecord(ev_csrb, s_side);
    k_gemm_wmma<IN_CH, false, false><<<(N_NODES + 63) / 64, B, 0, s_side>>>(
        x, W1, nullptr, p_hw);
    cudaEventRecord(ev_gemm, s_side);
    k_counts<<<(N_NODES + B - 1) / B, B, 0, s_side>>>(batch, p_counts);
    cudaEventRecord(ev_cnt, s_side);

    // main stream: first csr half (cnt zeroed by previous replay's last block)
    k_csr<<<(EHALF + B - 1) / B, B>>>(srcp, dstp, 0, EHALF, p_cnt, p_csr);
    cudaStreamWaitEvent(0, ev_csrb, 0);   // both halves done -> cnt final
    k_dinv<<<(N_NODES + B - 1) / B, B>>>(p_cnt, p_dinv);
    cudaStreamWaitEvent(0, ev_gemm, 0);   // gemm1 output ready

    // ---- layer 1 aggregate ----
    k_agg1<<<(N_NODES * 8 + B - 1) / B, B>>>(p_cnt, p_dinv, p_csr, p_hw, b1, p_agg1);

    // ---- layer 2: gemm with dinv-scaled epilogue, then fused agg+pool+final ----
    k_gemm_wmma<HID, true, true><<<(N_NODES + 63) / 64, B>>>(p_agg1, W2, p_dinv, p_hw);
    cudaStreamWaitEvent(0, ev_cnt, 0);    // counts histogram ready (read by final)
    k_agg2_final<<<(N_NODES * 8 + B - 1) / B, B>>>(
        p_cnt, p_dinv, p_csr, p_hw, b2, batch, p_pooled, p_counts,
        Wl, bl, out, p_cnt, p_ticket);
}

// round 15
// speedup vs baseline: 3.0479x; 3.0479x over previous
#include <cuda_runtime.h>
#include <cuda_fp16.h>
#include <cuda_bf16.h>
#include <mma.h>

using namespace nvcuda;

#define N_NODES   50000
#define N_EDGES   800000
#define IN_CH     128
#define HID       64
#define N_GRAPHS  256
#define N_CLASSES 10
#define CAP       64      // fixed bucket capacity (max degree ~40 for Poisson(16))

// ---------------- scratch (static device globals; no allocation) ------------
// Buffers that must start zeroed are re-zeroed at the END of each run
// (k_final_clean), so every replay starts from the same state.
__device__ int      g_cnt[N_NODES];            // per-node edge count
__device__ float    g_dinv[N_NODES];
__device__ int      g_csr[N_NODES * CAP];      // fixed-stride buckets of src ids
__device__ __half   g_hw[N_NODES * 64];        // X@W result, fp16 (both layers)
__device__ __half   g_agg1[N_NODES * 64];      // layer-1 output (post ReLU, fp16)
__device__ float    g_pooled[N_GRAPHS * 64];
__device__ int      g_counts[N_GRAPHS];

// ---------------- batch histogram (side stream) -------------------------------
__global__ void k_counts(const int* __restrict__ batch, int* __restrict__ counts) {
    int i = blockIdx.x * blockDim.x + threadIdx.x;
    if (i < N_NODES) atomicAdd(&counts[batch[i]], 1);
}

// bucket scatter over an edge range [base, base+count)
__global__ void k_csr(const int* __restrict__ src, const int* __restrict__ dst,
                      int base, int count,
                      int* __restrict__ cnt, int* __restrict__ csr) {
    int e = base + blockIdx.x * blockDim.x + threadIdx.x;
    if (e >= base + count) return;
    int s = src[e];
    int d = dst[e];
    int pos = atomicAdd(&cnt[d], 1);
    pos = min(pos, CAP - 1);   // safety clamp (never hit for this degree dist)
    csr[d * CAP + pos] = s;
}

// dinv from cnt (tiny)
__global__ void k_dinv(const int* __restrict__ cnt, float* __restrict__ dinv) {
    int i = blockIdx.x * blockDim.x + threadIdx.x;
    if (i < N_NODES) dinv[i] = rsqrtf((float)cnt[i] + 1.0f);
}

// ---------------- wmma GEMM: H[N x 64](fp16) = A[N x FIN] @ W[FIN x 64] -----
// SCALE: epilogue multiplies row by dinv[row] before fp16 pack (pre-scaled H).
template <int FIN, bool AHALF, bool SCALE>
__global__ __launch_bounds__(256) void k_gemm_wmma(
    const void* __restrict__ Ain, const float* __restrict__ W,
    const float* __restrict__ dinv, __half* __restrict__ H) {
    constexpr int LDA = FIN + 16;
    constexpr int LDW = 64 + 16;  // 80
    constexpr int LDC = 72;
    constexpr int A_BYTES = 64 * LDA * 2;
    constexpr int W_BYTES = FIN * LDW * 2;
    constexpr int C_BYTES = 64 * LDC * 4;
    constexpr int S_BYTES = (A_BYTES + W_BYTES) > C_BYTES ? (A_BYTES + W_BYTES) : C_BYTES;
    __shared__ __align__(32) char sraw[S_BYTES];
    __half* Ah = (__half*)sraw;
    __half* Wh = (__half*)(sraw + A_BYTES);
    float*  Cs = (float*)sraw;   // aliases Ah/Wh after compute is done

    const int t  = threadIdx.x;
    const int m0 = blockIdx.x * 64;

    if (AHALF) {
        const __half* A = (const __half*)Ain;
        for (int idx = t; idx < 64 * (FIN / 8); idx += 256) {
            int m  = idx / (FIN / 8);
            int kk = idx % (FIN / 8);
            int row = m0 + m;
            uint4 v = make_uint4(0u, 0u, 0u, 0u);
            if (row < N_NODES) v = *(const uint4*)(A + (size_t)row * FIN + kk * 8);
            *(uint4*)&Ah[m * LDA + kk * 8] = v;
        }
    } else {
        const float* A = (const float*)Ain;
        for (int idx = t; idx < 64 * (FIN / 4); idx += 256) {
            int m  = idx / (FIN / 4);
            int kk = idx % (FIN / 4);
            int row = m0 + m;
            float4 v = make_float4(0.f, 0.f, 0.f, 0.f);
            if (row < N_NODES) v = __ldg((const float4*)(A + (size_t)row * FIN) + kk);
            __half2 h0 = __floats2half2_rn(v.x, v.y);
            __half2 h1 = __floats2half2_rn(v.z, v.w);
            *(__half2*)&Ah[m * LDA + kk * 4]     = h0;
            *(__half2*)&Ah[m * LDA + kk * 4 + 2] = h1;
        }
    }
    for (int idx = t; idx < FIN * 16; idx += 256) {
        int k  = idx / 16;
        int c4 = idx % 16;
        float4 v = __ldg((const float4*)(W + (size_t)k * 64) + c4);
        __half2 h0 = __floats2half2_rn(v.x, v.y);
        __half2 h1 = __floats2half2_rn(v.z, v.w);
        *(__half2*)&Wh[k * LDW + c4 * 4]     = h0;
        *(__half2*)&Wh[k * LDW + c4 * 4 + 2] = h1;
    }
    __syncthreads();

    const int wid = t >> 5;
    const int wm  = wid >> 1;   // 0..3
    const int wn  = wid & 1;    // 0..1

    wmma::fragment<wmma::accumulator, 16, 16, 16, float> c0, c1;
    wmma::fill_fragment(c0, 0.0f);
    wmma::fill_fragment(c1, 0.0f);

#pragma unroll
    for (int k = 0; k < FIN; k += 16) {
        wmma::fragment<wmma::matrix_a, 16, 16, 16, __half, wmma::row_major> a;
        wmma::load_matrix_sync(a, &Ah[(wm * 16) * LDA + k], LDA);
        wmma::fragment<wmma::matrix_b, 16, 16, 16, __half, wmma::row_major> b0, b1;
        wmma::load_matrix_sync(b0, &Wh[k * LDW + wn * 32], LDW);
        wmma::load_matrix_sync(b1, &Wh[k * LDW + wn * 32 + 16], LDW);
        wmma::mma_sync(c0, a, b0, c0);
        wmma::mma_sync(c1, a, b1, c1);
    }

    __syncthreads();
    wmma::store_matrix_sync(&Cs[(wm * 16) * LDC + wn * 32],      c0, LDC, wmma::mem_row_major);
    wmma::store_matrix_sync(&Cs[(wm * 16) * LDC + wn * 32 + 16], c1, LDC, wmma::mem_row_major);
    __syncthreads();

    for (int idx = t; idx < 64 * 16; idx += 256) {
        int m  = idx >> 4;
        int c4 = idx & 15;
        int row = m0 + m;
        if (row < N_NODES) {
            float4 v = *(float4*)&Cs[m * LDC + c4 * 4];
            if (SCALE) {
                float di = dinv[row];
                v.x *= di; v.y *= di; v.z *= di; v.w *= di;
            }
            __half2 h0 = __floats2half2_rn(v.x, v.y);
            __half2 h1 = __floats2half2_rn(v.z, v.w);
            uint2 p = make_uint2(*(unsigned*)&h0, *(unsigned*)&h1);
            *(uint2*)(H + (size_t)row * 64 + c4 * 4) = p;
        }
    }
}

// ---------------- gather aggregation (fp16 gather, fp32 accumulate) ----------
__device__ __forceinline__ void acc_row(float acc[8], float nm, uint4 r) {
    float2 f0 = __half22float2(*(__half2*)&r.x);
    float2 f1 = __half22float2(*(__half2*)&r.y);
    float2 f2 = __half22float2(*(__half2*)&r.z);
    float2 f3 = __half22float2(*(__half2*)&r.w);
    acc[0] = fmaf(nm, f0.x, acc[0]); acc[1] = fmaf(nm, f0.y, acc[1]);
    acc[2] = fmaf(nm, f1.x, acc[2]); acc[3] = fmaf(nm, f1.y, acc[3]);
    acc[4] = fmaf(nm, f2.x, acc[4]); acc[5] = fmaf(nm, f2.y, acc[5]);
    acc[6] = fmaf(nm, f3.x, acc[6]); acc[7] = fmaf(nm, f3.y, acc[7]);
}

__device__ __forceinline__ void acc_row_add(float acc[8], uint4 r) {
    float2 f0 = __half22float2(*(__half2*)&r.x);
    float2 f1 = __half22float2(*(__half2*)&r.y);
    float2 f2 = __half22float2(*(__half2*)&r.z);
    float2 f3 = __half22float2(*(__half2*)&r.w);
    acc[0] += f0.x; acc[1] += f0.y;
    acc[2] += f1.x; acc[3] += f1.y;
    acc[4] += f2.x; acc[5] += f2.y;
    acc[6] += f3.x; acc[7] += f3.y;
}

// Layer 1: per-edge norm = dinv[src]*di; writes fp16, ReLU.
__global__ __launch_bounds__(256) void k_agg1(
    const int* __restrict__ cnt, const float* __restrict__ dinv,
    const int* __restrict__ csr, const __half* __restrict__ h,
    const float* __restrict__ bias, __half* __restrict__ out16) {
    int tid = blockIdx.x * blockDim.x + threadIdx.x;
    int n   = tid >> 3;
    int sub = tid & 7;
    if (n >= N_NODES) return;

    int deg = cnt[n];
    const int* bucket = csr + n * CAP;
    float di = dinv[n];

    float acc[8];
    {
        float s2 = di * di;
        uint4 raw = *(const uint4*)(h + (size_t)n * 64 + sub * 8);
        float4 bb0 = __ldg((const float4*)bias + sub * 2);
        float4 bb1 = __ldg((const float4*)bias + sub * 2 + 1);
        float2 f0 = __half22float2(*(__half2*)&raw.x);
        float2 f1 = __half22float2(*(__half2*)&raw.y);
        float2 f2 = __half22float2(*(__half2*)&raw.z);
        float2 f3 = __half22float2(*(__half2*)&raw.w);
        acc[0] = fmaf(f0.x, s2, bb0.x); acc[1] = fmaf(f0.y, s2, bb0.y);
        acc[2] = fmaf(f1.x, s2, bb0.z); acc[3] = fmaf(f1.y, s2, bb0.w);
        acc[4] = fmaf(f2.x, s2, bb1.x); acc[5] = fmaf(f2.y, s2, bb1.y);
        acc[6] = fmaf(f3.x, s2, bb1.z); acc[7] = fmaf(f3.y, s2, bb1.w);
    }

    int j = 0;
    for (; j + 4 <= deg; j += 4) {
        int4 sv = *(const int4*)(bucket + j);
        float n0 = dinv[sv.x] * di;
        float n1 = dinv[sv.y] * di;
        float n2 = dinv[sv.z] * di;
        float n3 = dinv[sv.w] * di;
        uint4 r0 = *(const uint4*)(h + (size_t)sv.x * 64 + sub * 8);
        uint4 r1 = *(const uint4*)(h + (size_t)sv.y * 64 + sub * 8);
        uint4 r2 = *(const uint4*)(h + (size_t)sv.z * 64 + sub * 8);
        uint4 r3 = *(const uint4*)(h + (size_t)sv.w * 64 + sub * 8);
        acc_row(acc, n0, r0);
        acc_row(acc, n1, r1);
        acc_row(acc, n2, r2);
        acc_row(acc, n3, r3);
    }
    for (; j < deg; j++) {
        int s0 = bucket[j];
        float n0 = dinv[s0] * di;
        uint4 r0 = *(const uint4*)(h + (size_t)s0 * 64 + sub * 8);
        acc_row(acc, n0, r0);
    }

#pragma unroll
    for (int c = 0; c < 8; c++) acc[c] = fmaxf(acc[c], 0.0f);

    __half2 h0 = __floats2half2_rn(acc[0], acc[1]);
    __half2 h1 = __floats2half2_rn(acc[2], acc[3]);
    __half2 h2 = __floats2half2_rn(acc[4], acc[5]);
    __half2 h3 = __floats2half2_rn(acc[6], acc[7]);
    uint4 p = make_uint4(*(unsigned*)&h0, *(unsigned*)&h1,
                         *(unsigned*)&h2, *(unsigned*)&h3);
    *(uint4*)(out16 + (size_t)n * 64 + sub * 8) = p;
}

// Layer 2 aggregate (hs PRE-SCALED by dinv; pure-sum inner loop) + mean-pool.
__global__ __launch_bounds__(256) void k_agg2_pool(
    const int* __restrict__ cnt, const float* __restrict__ dinv,
    const int* __restrict__ csr, const __half* __restrict__ hs,
    const float* __restrict__ bias, const int* __restrict__ batch,
    float* __restrict__ pooled) {
    int tid = blockIdx.x * blockDim.x + threadIdx.x;
    int n   = tid >> 3;
    int sub = tid & 7;
    if (n >= N_NODES) return;

    int deg = cnt[n];
    const int* bucket = csr + n * CAP;
    float di = dinv[n];

    float acc[8];
    {
        uint4 raw = *(const uint4*)(hs + (size_t)n * 64 + sub * 8);
        float2 f0 = __half22float2(*(__half2*)&raw.x);
        float2 f1 = __half22float2(*(__half2*)&raw.y);
        float2 f2 = __half22float2(*(__half2*)&raw.z);
        float2 f3 = __half22float2(*(__half2*)&raw.w);
        acc[0] = f0.x; acc[1] = f0.y; acc[2] = f1.x; acc[3] = f1.y;
        acc[4] = f2.x; acc[5] = f2.y; acc[6] = f3.x; acc[7] = f3.y;
    }

    int j = 0;
    for (; j + 4 <= deg; j += 4) {
        int4 sv = *(const int4*)(bucket + j);
        uint4 r0 = *(const uint4*)(hs + (size_t)sv.x * 64 + sub * 8);
        uint4 r1 = *(const uint4*)(hs + (size_t)sv.y * 64 + sub * 8);
        uint4 r2 = *(const uint4*)(hs + (size_t)sv.z * 64 + sub * 8);
        uint4 r3 = *(const uint4*)(hs + (size_t)sv.w * 64 + sub * 8);
        acc_row_add(acc, r0);
        acc_row_add(acc, r1);
        acc_row_add(acc, r2);
        acc_row_add(acc, r3);
    }
    for (; j < deg; j++) {
        int s0 = bucket[j];
        uint4 r0 = *(const uint4*)(hs + (size_t)s0 * 64 + sub * 8);
        acc_row_add(acc, r0);
    }

    float4 bb0 = __ldg((const float4*)bias + sub * 2);
    float4 bb1 = __ldg((const float4*)bias + sub * 2 + 1);
    float4 a0 = make_float4(fmaf(acc[0], di, bb0.x), fmaf(acc[1], di, bb0.y),
                            fmaf(acc[2], di, bb0.z), fmaf(acc[3], di, bb0.w));
    float4 a1 = make_float4(fmaf(acc[4], di, bb1.x), fmaf(acc[5], di, bb1.y),
                            fmaf(acc[6], di, bb1.z), fmaf(acc[7], di, bb1.w));

    int g = batch[n];
    atomicAdd((float4*)&pooled[(size_t)g * 64 + sub * 8], a0);
    atomicAdd((float4*)&pooled[(size_t)g * 64 + sub * 8 + 4], a1);
}

// ---------------- classifier + end-of-run scratch cleanup --------------------
__global__ __launch_bounds__(320) void k_final_clean(
    const float* __restrict__ pooled, const int* __restrict__ counts,
    const float* __restrict__ Wl, const float* __restrict__ bl,
    float* __restrict__ out,
    float* __restrict__ pooled_w, int* __restrict__ counts_w,
    int* __restrict__ cnt_w) {
    int t   = threadIdx.x;
    int tid = blockIdx.x * 320 + t;
    if (tid < N_GRAPHS * N_CLASSES) {
        int g = tid / N_CLASSES;
        int j = tid - g * N_CLASSES;
        float s = 0.0f;
#pragma unroll
        for (int c = 0; c < 64; c++) s += pooled[g * 64 + c] * Wl[c * N_CLASSES + j];
        float cn = fmaxf((float)counts[g], 1.0f);
        out[tid] = s / cn + bl[j];
    }
    __syncthreads();
    int base = blockIdx.x * 32 * 64;
    for (int i = t; i < 32 * 64; i += 320) pooled_w[base + i] = 0.0f;
    if (t < 32) counts_w[blockIdx.x * 32 + t] = 0;
    for (int i = tid; i < N_NODES; i += 8 * 320) cnt_w[i] = 0;
}

// ---------------- host launch -------------------------------------------------
template <typename T, typename S>
static T* sym_addr(const S& sym) {
    void* p = nullptr;
    cudaGetSymbolAddress(&p, sym);
    return (T*)p;
}

extern "C" void kernel_launch(void* const* d_in, const int* in_sizes, int n_in,
                              void* d_out, int out_size) {
    const float* x     = (const float*)d_in[0];
    const int*   ei    = (const int*)d_in[1];
    const int*   srcp  = ei;
    const int*   dstp  = ei + N_EDGES;
    const int*   batch = (const int*)d_in[3];
    const float* W1 = (const float*)d_in[4];
    const float* b1 = (const float*)d_in[5];
    const float* W2 = (const float*)d_in[6];
    const float* b2 = (const float*)d_in[7];
    const float* Wl = (const float*)d_in[8];
    const float* bl = (const float*)d_in[9];
    float* out = (float*)d_out;

    static int*      p_cnt    = nullptr;
    static float*    p_dinv   = nullptr;
    static int*      p_csr    = nullptr;
    static __half*   p_hw     = nullptr;
    static __half*   p_agg1   = nullptr;
    static float*    p_pooled = nullptr;
    static int*      p_counts = nullptr;
    static cudaStream_t s1 = nullptr, s2 = nullptr;
    static cudaEvent_t  ev_fork = nullptr, ev_csrb = nullptr,
                        ev_gemm = nullptr, ev_cnt = nullptr;
    if (!p_cnt) {
        p_cnt    = sym_addr<int>(g_cnt);
        p_dinv   = sym_addr<float>(g_dinv);
        p_csr    = sym_addr<int>(g_csr);
        p_hw     = sym_addr<__half>(g_hw);
        p_agg1   = sym_addr<__half>(g_agg1);
        p_pooled = sym_addr<float>(g_pooled);
        p_counts = sym_addr<int>(g_counts);
        cudaStreamCreateWithFlags(&s1, cudaStreamNonBlocking);
        cudaStreamCreateWithFlags(&s2, cudaStreamNonBlocking);
        cudaEventCreateWithFlags(&ev_fork, cudaEventDisableTiming);
        cudaEventCreateWithFlags(&ev_csrb, cudaEventDisableTiming);
        cudaEventCreateWithFlags(&ev_gemm, cudaEventDisableTiming);
        cudaEventCreateWithFlags(&ev_cnt,  cudaEventDisableTiming);
    }

    const int B = 256;
    const int EHALF = N_EDGES / 2;

    // fork
    cudaEventRecord(ev_fork, 0);
    cudaStreamWaitEvent(s1, ev_fork, 0);
    cudaStreamWaitEvent(s2, ev_fork, 0);

    // s1: second csr half, then batch counts
    k_csr<<<(EHALF + B - 1) / B, B, 0, s1>>>(srcp, dstp, EHALF, EHALF, p_cnt, p_csr);
    cudaEventRecord(ev_csrb, s1);
    k_counts<<<(N_NODES + B - 1) / B, B, 0, s1>>>(batch, p_counts);
    cudaEventRecord(ev_cnt, s1);

    // s2: gemm1, fully concurrent with both csr halves
    k_gemm_wmma<IN_CH, false, false><<<(N_NODES + 63) / 64, B, 0, s2>>>(
        x, W1, nullptr, p_hw);
    cudaEventRecord(ev_gemm, s2);

    // main: first csr half (cnt zeroed by previous replay's k_final_clean)
    k_csr<<<(EHALF + B - 1) / B, B>>>(srcp, dstp, 0, EHALF, p_cnt, p_csr);
    cudaStreamWaitEvent(0, ev_csrb, 0);   // both halves done -> cnt final
    k_dinv<<<(N_NODES + B - 1) / B, B>>>(p_cnt, p_dinv);
    cudaStreamWaitEvent(0, ev_gemm, 0);   // gemm1 output ready

    // ---- layer 1 aggregate ----
    k_agg1<<<(N_NODES * 8 + B - 1) / B, B>>>(p_cnt, p_dinv, p_csr, p_hw, b1, p_agg1);

    // ---- layer 2: gemm with dinv-scaled epilogue, then agg+pool ----
    k_gemm_wmma<HID, true, true><<<(N_NODES + 63) / 64, B>>>(p_agg1, W2, p_dinv, p_hw);
    k_agg2_pool<<<(N_NODES * 8 + B - 1) / B, B>>>(
        p_cnt, p_dinv, p_csr, p_hw, b2, batch, p_pooled);

    // ---- classifier + scratch cleanup for the next replay ----
    cudaStreamWaitEvent(0, ev_cnt, 0);    // counts histogram ready
    k_final_clean<<<8, 320>>>(p_pooled, p_counts, Wl, bl, out,
                              p_pooled, p_counts, p_cnt);
}

// round 16
// speedup vs baseline: 3.2129x; 1.0541x over previous
#include <cuda_runtime.h>
#include <cuda_fp16.h>
#include <cuda_bf16.h>
#include <mma.h>

using namespace nvcuda;

#define N_NODES   50000
#define N_EDGES   800000
#define IN_CH     128
#define HID       64
#define N_GRAPHS  256
#define N_CLASSES 10
#define CAP       64      // fixed bucket capacity (max degree ~40 for Poisson(16))

// ---------------- scratch (static device globals; no allocation) ------------
// Buffers that must start zeroed are re-zeroed at the END of each run
// (k_final_clean), so every replay starts from the same state.
__device__ int      g_cnt[N_NODES];            // per-node edge count (csr build)
__device__ int      g_deg[N_NODES];            // independent degree histogram
__device__ float    g_dinv[N_NODES];
__device__ int      g_csr[N_NODES * CAP];      // fixed-stride buckets of src ids
__device__ __half   g_hw[N_NODES * 64];        // X@W result, fp16 (both layers)
__device__ __half   g_agg1[N_NODES * 64];      // layer-1 output (post ReLU, fp16)
__device__ float    g_pooled[N_GRAPHS * 64];
__device__ int      g_counts[N_GRAPHS];

// ---------------- batch histogram --------------------------------------------
__global__ void k_counts(const int* __restrict__ batch, int* __restrict__ counts) {
    int i = blockIdx.x * blockDim.x + threadIdx.x;
    if (i < N_NODES) atomicAdd(&counts[batch[i]], 1);
}

// independent degree histogram (separate array; concurrent with csr build)
__global__ void k_deg(const int* __restrict__ dst, int* __restrict__ deg) {
    int e = blockIdx.x * blockDim.x + threadIdx.x;
    if (e < N_EDGES) atomicAdd(&deg[dst[e]], 1);
}

// bucket scatter over an edge range [base, base+count)
__global__ void k_csr(const int* __restrict__ src, const int* __restrict__ dst,
                      int base, int count,
                      int* __restrict__ cnt, int* __restrict__ csr) {
    int e = base + blockIdx.x * blockDim.x + threadIdx.x;
    if (e >= base + count) return;
    int s = src[e];
    int d = dst[e];
    int pos = atomicAdd(&cnt[d], 1);
    pos = min(pos, CAP - 1);   // safety clamp (never hit for this degree dist)
    csr[d * CAP + pos] = s;
}

// dinv from deg (tiny; runs on its own stream, off the csr critical path)
__global__ void k_dinv(const int* __restrict__ deg, float* __restrict__ dinv) {
    int i = blockIdx.x * blockDim.x + threadIdx.x;
    if (i < N_NODES) dinv[i] = rsqrtf((float)deg[i] + 1.0f);
}

// ---------------- wmma GEMM: H[N x 64](fp16) = A[N x FIN] @ W[FIN x 64] -----
// SCALE: epilogue multiplies row by dinv[row] before fp16 pack (pre-scaled H).
template <int FIN, bool AHALF, bool SCALE>
__global__ __launch_bounds__(256) void k_gemm_wmma(
    const void* __restrict__ Ain, const float* __restrict__ W,
    const float* __restrict__ dinv, __half* __restrict__ H) {
    constexpr int LDA = FIN + 16;
    constexpr int LDW = 64 + 16;  // 80
    constexpr int LDC = 72;
    constexpr int A_BYTES = 64 * LDA * 2;
    constexpr int W_BYTES = FIN * LDW * 2;
    constexpr int C_BYTES = 64 * LDC * 4;
    constexpr int S_BYTES = (A_BYTES + W_BYTES) > C_BYTES ? (A_BYTES + W_BYTES) : C_BYTES;
    __shared__ __align__(32) char sraw[S_BYTES];
    __half* Ah = (__half*)sraw;
    __half* Wh = (__half*)(sraw + A_BYTES);
    float*  Cs = (float*)sraw;   // aliases Ah/Wh after compute is done

    const int t  = threadIdx.x;
    const int m0 = blockIdx.x * 64;

    if (AHALF) {
        const __half* A = (const __half*)Ain;
        for (int idx = t; idx < 64 * (FIN / 8); idx += 256) {
            int m  = idx / (FIN / 8);
            int kk = idx % (FIN / 8);
            int row = m0 + m;
            uint4 v = make_uint4(0u, 0u, 0u, 0u);
            if (row < N_NODES) v = *(const uint4*)(A + (size_t)row * FIN + kk * 8);
            *(uint4*)&Ah[m * LDA + kk * 8] = v;
        }
    } else {
        const float* A = (const float*)Ain;
        for (int idx = t; idx < 64 * (FIN / 4); idx += 256) {
            int m  = idx / (FIN / 4);
            int kk = idx % (FIN / 4);
            int row = m0 + m;
            float4 v = make_float4(0.f, 0.f, 0.f, 0.f);
            if (row < N_NODES) v = __ldg((const float4*)(A + (size_t)row * FIN) + kk);
            __half2 h0 = __floats2half2_rn(v.x, v.y);
            __half2 h1 = __floats2half2_rn(v.z, v.w);
            *(__half2*)&Ah[m * LDA + kk * 4]     = h0;
            *(__half2*)&Ah[m * LDA + kk * 4 + 2] = h1;
        }
    }
    for (int idx = t; idx < FIN * 16; idx += 256) {
        int k  = idx / 16;
        int c4 = idx % 16;
        float4 v = __ldg((const float4*)(W + (size_t)k * 64) + c4);
        __half2 h0 = __floats2half2_rn(v.x, v.y);
        __half2 h1 = __floats2half2_rn(v.z, v.w);
        *(__half2*)&Wh[k * LDW + c4 * 4]     = h0;
        *(__half2*)&Wh[k * LDW + c4 * 4 + 2] = h1;
    }
    __syncthreads();

    const int wid = t >> 5;
    const int wm  = wid >> 1;   // 0..3
    const int wn  = wid & 1;    // 0..1

    wmma::fragment<wmma::accumulator, 16, 16, 16, float> c0, c1;
    wmma::fill_fragment(c0, 0.0f);
    wmma::fill_fragment(c1, 0.0f);

#pragma unroll
    for (int k = 0; k < FIN; k += 16) {
        wmma::fragment<wmma::matrix_a, 16, 16, 16, __half, wmma::row_major> a;
        wmma::load_matrix_sync(a, &Ah[(wm * 16) * LDA + k], LDA);
        wmma::fragment<wmma::matrix_b, 16, 16, 16, __half, wmma::row_major> b0, b1;
        wmma::load_matrix_sync(b0, &Wh[k * LDW + wn * 32], LDW);
        wmma::load_matrix_sync(b1, &Wh[k * LDW + wn * 32 + 16], LDW);
        wmma::mma_sync(c0, a, b0, c0);
        wmma::mma_sync(c1, a, b1, c1);
    }

    __syncthreads();
    wmma::store_matrix_sync(&Cs[(wm * 16) * LDC + wn * 32],      c0, LDC, wmma::mem_row_major);
    wmma::store_matrix_sync(&Cs[(wm * 16) * LDC + wn * 32 + 16], c1, LDC, wmma::mem_row_major);
    __syncthreads();

    for (int idx = t; idx < 64 * 16; idx += 256) {
        int m  = idx >> 4;
        int c4 = idx & 15;
        int row = m0 + m;
        if (row < N_NODES) {
            float4 v = *(float4*)&Cs[m * LDC + c4 * 4];
            if (SCALE) {
                float di = dinv[row];
                v.x *= di; v.y *= di; v.z *= di; v.w *= di;
            }
            __half2 h0 = __floats2half2_rn(v.x, v.y);
            __half2 h1 = __floats2half2_rn(v.z, v.w);
            uint2 p = make_uint2(*(unsigned*)&h0, *(unsigned*)&h1);
            *(uint2*)(H + (size_t)row * 64 + c4 * 4) = p;
        }
    }
}

// ---------------- gather aggregation (fp16 gather, fp32 accumulate) ----------
__device__ __forceinline__ void acc_row(float acc[8], float nm, uint4 r) {
    float2 f0 = __half22float2(*(__half2*)&r.x);
    float2 f1 = __half22float2(*(__half2*)&r.y);
    float2 f2 = __half22float2(*(__half2*)&r.z);
    float2 f3 = __half22float2(*(__half2*)&r.w);
    acc[0] = fmaf(nm, f0.x, acc[0]); acc[1] = fmaf(nm, f0.y, acc[1]);
    acc[2] = fmaf(nm, f1.x, acc[2]); acc[3] = fmaf(nm, f1.y, acc[3]);
    acc[4] = fmaf(nm, f2.x, acc[4]); acc[5] = fmaf(nm, f2.y, acc[5]);
    acc[6] = fmaf(nm, f3.x, acc[6]); acc[7] = fmaf(nm, f3.y, acc[7]);
}

__device__ __forceinline__ void acc_row_add(float acc[8], uint4 r) {
    float2 f0 = __half22float2(*(__half2*)&r.x);
    float2 f1 = __half22float2(*(__half2*)&r.y);
    float2 f2 = __half22float2(*(__half2*)&r.z);
    float2 f3 = __half22float2(*(__half2*)&r.w);
    acc[0] += f0.x; acc[1] += f0.y;
    acc[2] += f1.x; acc[3] += f1.y;
    acc[4] += f2.x; acc[5] += f2.y;
    acc[6] += f3.x; acc[7] += f3.y;
}

// Layer 1: per-edge norm = dinv[src]*di; writes fp16, ReLU.
__global__ __launch_bounds__(256) void k_agg1(
    const int* __restrict__ cnt, const float* __restrict__ dinv,
    const int* __restrict__ csr, const __half* __restrict__ h,
    const float* __restrict__ bias, __half* __restrict__ out16) {
    int tid = blockIdx.x * blockDim.x + threadIdx.x;
    int n   = tid >> 3;
    int sub = tid & 7;
    if (n >= N_NODES) return;

    int deg = cnt[n];
    const int* bucket = csr + n * CAP;
    float di = dinv[n];

    float acc[8];
    {
        float s2 = di * di;
        uint4 raw = *(const uint4*)(h + (size_t)n * 64 + sub * 8);
        float4 bb0 = __ldg((const float4*)bias + sub * 2);
        float4 bb1 = __ldg((const float4*)bias + sub * 2 + 1);
        float2 f0 = __half22float2(*(__half2*)&raw.x);
        float2 f1 = __half22float2(*(__half2*)&raw.y);
        float2 f2 = __half22float2(*(__half2*)&raw.z);
        float2 f3 = __half22float2(*(__half2*)&raw.w);
        acc[0] = fmaf(f0.x, s2, bb0.x); acc[1] = fmaf(f0.y, s2, bb0.y);
        acc[2] = fmaf(f1.x, s2, bb0.z); acc[3] = fmaf(f1.y, s2, bb0.w);
        acc[4] = fmaf(f2.x, s2, bb1.x); acc[5] = fmaf(f2.y, s2, bb1.y);
        acc[6] = fmaf(f3.x, s2, bb1.z); acc[7] = fmaf(f3.y, s2, bb1.w);
    }

    int j = 0;
    for (; j + 4 <= deg; j += 4) {
        int4 sv = *(const int4*)(bucket + j);
        float n0 = dinv[sv.x] * di;
        float n1 = dinv[sv.y] * di;
        float n2 = dinv[sv.z] * di;
        float n3 = dinv[sv.w] * di;
        uint4 r0 = *(const uint4*)(h + (size_t)sv.x * 64 + sub * 8);
        uint4 r1 = *(const uint4*)(h + (size_t)sv.y * 64 + sub * 8);
        uint4 r2 = *(const uint4*)(h + (size_t)sv.z * 64 + sub * 8);
        uint4 r3 = *(const uint4*)(h + (size_t)sv.w * 64 + sub * 8);
        acc_row(acc, n0, r0);
        acc_row(acc, n1, r1);
        acc_row(acc, n2, r2);
        acc_row(acc, n3, r3);
    }
    for (; j < deg; j++) {
        int s0 = bucket[j];
        float n0 = dinv[s0] * di;
        uint4 r0 = *(const uint4*)(h + (size_t)s0 * 64 + sub * 8);
        acc_row(acc, n0, r0);
    }

#pragma unroll
    for (int c = 0; c < 8; c++) acc[c] = fmaxf(acc[c], 0.0f);

    __half2 h0 = __floats2half2_rn(acc[0], acc[1]);
    __half2 h1 = __floats2half2_rn(acc[2], acc[3]);
    __half2 h2 = __floats2half2_rn(acc[4], acc[5]);
    __half2 h3 = __floats2half2_rn(acc[6], acc[7]);
    uint4 p = make_uint4(*(unsigned*)&h0, *(unsigned*)&h1,
                         *(unsigned*)&h2, *(unsigned*)&h3);
    *(uint4*)(out16 + (size_t)n * 64 + sub * 8) = p;
}

// Layer 2 aggregate (hs PRE-SCALED by dinv; pure-sum inner loop) + mean-pool.
__global__ __launch_bounds__(256) void k_agg2_pool(
    const int* __restrict__ cnt, const float* __restrict__ dinv,
    const int* __restrict__ csr, const __half* __restrict__ hs,
    const float* __restrict__ bias, const int* __restrict__ batch,
    float* __restrict__ pooled) {
    int tid = blockIdx.x * blockDim.x + threadIdx.x;
    int n   = tid >> 3;
    int sub = tid & 7;
    if (n >= N_NODES) return;

    int deg = cnt[n];
    const int* bucket = csr + n * CAP;
    float di = dinv[n];

    float acc[8];
    {
        uint4 raw = *(const uint4*)(hs + (size_t)n * 64 + sub * 8);
        float2 f0 = __half22float2(*(__half2*)&raw.x);
        float2 f1 = __half22float2(*(__half2*)&raw.y);
        float2 f2 = __half22float2(*(__half2*)&raw.z);
        float2 f3 = __half22float2(*(__half2*)&raw.w);
        acc[0] = f0.x; acc[1] = f0.y; acc[2] = f1.x; acc[3] = f1.y;
        acc[4] = f2.x; acc[5] = f2.y; acc[6] = f3.x; acc[7] = f3.y;
    }

    int j = 0;
    for (; j + 4 <= deg; j += 4) {
        int4 sv = *(const int4*)(bucket + j);
        uint4 r0 = *(const uint4*)(hs + (size_t)sv.x * 64 + sub * 8);
        uint4 r1 = *(const uint4*)(hs + (size_t)sv.y * 64 + sub * 8);
        uint4 r2 = *(const uint4*)(hs + (size_t)sv.z * 64 + sub * 8);
        uint4 r3 = *(const uint4*)(hs + (size_t)sv.w * 64 + sub * 8);
        acc_row_add(acc, r0);
        acc_row_add(acc, r1);
        acc_row_add(acc, r2);
        acc_row_add(acc, r3);
    }
    for (; j < deg; j++) {
        int s0 = bucket[j];
        uint4 r0 = *(const uint4*)(hs + (size_t)s0 * 64 + sub * 8);
        acc_row_add(acc, r0);
    }

    float4 bb0 = __ldg((const float4*)bias + sub * 2);
    float4 bb1 = __ldg((const float4*)bias + sub * 2 + 1);
    float4 a0 = make_float4(fmaf(acc[0], di, bb0.x), fmaf(acc[1], di, bb0.y),
                            fmaf(acc[2], di, bb0.z), fmaf(acc[3], di, bb0.w));
    float4 a1 = make_float4(fmaf(acc[4], di, bb1.x), fmaf(acc[5], di, bb1.y),
                            fmaf(acc[6], di, bb1.z), fmaf(acc[7], di, bb1.w));

    int g = batch[n];
    atomicAdd((float4*)&pooled[(size_t)g * 64 + sub * 8], a0);
    atomicAdd((float4*)&pooled[(size_t)g * 64 + sub * 8 + 4], a1);
}

// ---------------- classifier + end-of-run scratch cleanup --------------------
__global__ __launch_bounds__(320) void k_final_clean(
    const float* __restrict__ pooled, const int* __restrict__ counts,
    const float* __restrict__ Wl, const float* __restrict__ bl,
    float* __restrict__ out,
    float* __restrict__ pooled_w, int* __restrict__ counts_w,
    int* __restrict__ cnt_w, int* __restrict__ deg_w) {
    int t   = threadIdx.x;
    int tid = blockIdx.x * 320 + t;
    if (tid < N_GRAPHS * N_CLASSES) {
        int g = tid / N_CLASSES;
        int j = tid - g * N_CLASSES;
        float s = 0.0f;
#pragma unroll
        for (int c = 0; c < 64; c++) s += pooled[g * 64 + c] * Wl[c * N_CLASSES + j];
        float cn = fmaxf((float)counts[g], 1.0f);
        out[tid] = s / cn + bl[j];
    }
    __syncthreads();
    int base = blockIdx.x * 32 * 64;
    for (int i = t; i < 32 * 64; i += 320) pooled_w[base + i] = 0.0f;
    if (t < 32) counts_w[blockIdx.x * 32 + t] = 0;
    for (int i = tid; i < N_NODES; i += 8 * 320) { cnt_w[i] = 0; deg_w[i] = 0; }
}

// ---------------- host launch -------------------------------------------------
template <typename T, typename S>
static T* sym_addr(const S& sym) {
    void* p = nullptr;
    cudaGetSymbolAddress(&p, sym);
    return (T*)p;
}

extern "C" void kernel_launch(void* const* d_in, const int* in_sizes, int n_in,
                              void* d_out, int out_size) {
    const float* x     = (const float*)d_in[0];
    const int*   ei    = (const int*)d_in[1];
    const int*   srcp  = ei;
    const int*   dstp  = ei + N_EDGES;
    const int*   batch = (const int*)d_in[3];
    const float* W1 = (const float*)d_in[4];
    const float* b1 = (const float*)d_in[5];
    const float* W2 = (const float*)d_in[6];
    const float* b2 = (const float*)d_in[7];
    const float* Wl = (const float*)d_in[8];
    const float* bl = (const float*)d_in[9];
    float* out = (float*)d_out;

    static int*      p_cnt    = nullptr;
    static int*      p_deg    = nullptr;
    static float*    p_dinv   = nullptr;
    static int*      p_csr    = nullptr;
    static __half*   p_hw     = nullptr;
    static __half*   p_agg1   = nullptr;
    static float*    p_pooled = nullptr;
    static int*      p_counts = nullptr;
    static cudaStream_t s1 = nullptr, s2 = nullptr, s3 = nullptr;
    static cudaEvent_t  ev_fork = nullptr, ev_csrb = nullptr,
                        ev_gemm = nullptr, ev_cnt = nullptr, ev_dinv = nullptr;
    if (!p_cnt) {
        p_cnt    = sym_addr<int>(g_cnt);
        p_deg    = sym_addr<int>(g_deg);
        p_dinv   = sym_addr<float>(g_dinv);
        p_csr    = sym_addr<int>(g_csr);
        p_hw     = sym_addr<__half>(g_hw);
        p_agg1   = sym_addr<__half>(g_agg1);
        p_pooled = sym_addr<float>(g_pooled);
        p_counts = sym_addr<int>(g_counts);
        cudaStreamCreateWithFlags(&s1, cudaStreamNonBlocking);
        cudaStreamCreateWithFlags(&s2, cudaStreamNonBlocking);
        cudaStreamCreateWithFlags(&s3, cudaStreamNonBlocking);
        cudaEventCreateWithFlags(&ev_fork, cudaEventDisableTiming);
        cudaEventCreateWithFlags(&ev_csrb, cudaEventDisableTiming);
        cudaEventCreateWithFlags(&ev_gemm, cudaEventDisableTiming);
        cudaEventCreateWithFlags(&ev_cnt,  cudaEventDisableTiming);
        cudaEventCreateWithFlags(&ev_dinv, cudaEventDisableTiming);
    }

    const int B = 256;
    const int EHALF = N_EDGES / 2;

    // fork
    cudaEventRecord(ev_fork, 0);
    cudaStreamWaitEvent(s1, ev_fork, 0);
    cudaStreamWaitEvent(s2, ev_fork, 0);
    cudaStreamWaitEvent(s3, ev_fork, 0);

    // s1: second csr half, then batch counts
    k_csr<<<(EHALF + B - 1) / B, B, 0, s1>>>(srcp, dstp, EHALF, EHALF, p_cnt, p_csr);
    cudaEventRecord(ev_csrb, s1);
    k_counts<<<(N_NODES + B - 1) / B, B, 0, s1>>>(batch, p_counts);
    cudaEventRecord(ev_cnt, s1);

    // s2: gemm1, concurrent with csr halves
    k_gemm_wmma<IN_CH, false, false><<<(N_NODES + 63) / 64, B, 0, s2>>>(
        x, W1, nullptr, p_hw);
    cudaEventRecord(ev_gemm, s2);

    // s3: independent degree histogram -> dinv (off the csr critical path)
    k_deg<<<(N_EDGES + B - 1) / B, B, 0, s3>>>(dstp, p_deg);
    k_dinv<<<(N_NODES + B - 1) / B, B, 0, s3>>>(p_deg, p_dinv);
    cudaEventRecord(ev_dinv, s3);

    // main: first csr half (cnt/deg zeroed by previous replay's k_final_clean)
    k_csr<<<(EHALF + B - 1) / B, B>>>(srcp, dstp, 0, EHALF, p_cnt, p_csr);
    cudaStreamWaitEvent(0, ev_csrb, 0);   // both csr halves done
    cudaStreamWaitEvent(0, ev_dinv, 0);   // dinv ready
    cudaStreamWaitEvent(0, ev_gemm, 0);   // gemm1 output ready

    // ---- layer 1 aggregate ----
    k_agg1<<<(N_NODES * 8 + B - 1) / B, B>>>(p_cnt, p_dinv, p_csr, p_hw, b1, p_agg1);

    // ---- layer 2: gemm with dinv-scaled epilogue, then agg+pool ----
    k_gemm_wmma<HID, true, true><<<(N_NODES + 63) / 64, B>>>(p_agg1, W2, p_dinv, p_hw);
    k_agg2_pool<<<(N_NODES * 8 + B - 1) / B, B>>>(
        p_cnt, p_dinv, p_csr, p_hw, b2, batch, p_pooled);

    // ---- classifier + scratch cleanup for the next replay ----
    cudaStreamWaitEvent(0, ev_cnt, 0);    // counts histogram ready
    k_final_clean<<<8, 320>>>(p_pooled, p_counts, Wl, bl, out,
                              p_pooled, p_counts, p_cnt, p_deg);
}